// round 13
// baseline (speedup 1.0000x reference)
#include <cuda_runtime.h>

#define BB 2
#define CC 128
#define HH 128
#define WW 256
#define KK 20
#define HW (HH * WW)
#define EPSV 1e-12f

typedef unsigned long long u64;

__device__ __forceinline__ u64 pk2(float lo, float hi) {
    u64 r; asm("mov.b64 %0, {%1,%2};" : "=l"(r) : "f"(lo), "f"(hi)); return r;
}
__device__ __forceinline__ void upk2(u64 v, float& lo, float& hi) {
    asm("mov.b64 {%0,%1}, %2;" : "=f"(lo), "=f"(hi) : "l"(v));
}
__device__ __forceinline__ u64 fma2_(u64 a, u64 b, u64 c) {
    u64 d; asm("fma.rn.f32x2 %0, %1, %2, %3;" : "=l"(d) : "l"(a), "l"(b), "l"(c)); return d;
}
__device__ __forceinline__ u64 mul2_(u64 a, u64 b) {
    u64 d; asm("mul.rn.f32x2 %0, %1, %2;" : "=l"(d) : "l"(a), "l"(b)); return d;
}
__device__ __forceinline__ u64 add2_(u64 a, u64 b) {
    u64 d; asm("add.rn.f32x2 %0, %1, %2;" : "=l"(d) : "l"(a), "l"(b)); return d;
}
__device__ __forceinline__ float wred(float v) {
#pragma unroll
    for (int o = 16; o > 0; o >>= 1) v += __shfl_xor_sync(0xffffffffu, v, o);
    return v;
}
__device__ __forceinline__ float dot4(float4 a) {
    return a.x * a.x + a.y * a.y + a.z * a.z + a.w * a.w;
}

// High-ILP fused kernel. Block = (b,h), 256 threads, 128 regs/thread.
// tid: pxg bits0-5 (64 groups x 4 px), cq bits6-7 (4 c-quarters of 32).
// Each thread: 4 px x ALL 20 k x 32 c -> acc[2][20] (80 regs), x loaded ONCE.
__global__ __launch_bounds__(256, 2) void iso_kernel(const float* __restrict__ f,
                                                     const float* __restrict__ p,
                                                     const float* __restrict__ ds,
                                                     float* __restrict__ out) {
    __shared__ u64 s_pn[CC * 20];    // [c][k] folded protos (20 KB); aliased as s_red after
    __shared__ u64 s_s2p[4 * 128];   // s2 partials per cq (4 KB)
    __shared__ u64 s_s2[128];        // final ||fn||^2 per pixel pair
    __shared__ u64 s_r2[CC];         // inv_c^2 dup-packed
    __shared__ float s_inv[CC];
    __shared__ float s_pinv[KK];
    __shared__ float s_pn2[KK];

    int tid = threadIdx.x;
    int w = tid >> 5, lane = tid & 31;
    int b = blockIdx.x / HH, h = blockIdx.x % HH;
    const float* fbh = f + (size_t)b * CC * HW + (size_t)h * WW;

    // ---- Pass 1a: W-norms. Warp w (of 8) handles c = w + 8j, j<16; 2-row batches.
#pragma unroll
    for (int m = 0; m < 16; m += 2) {
        int cA = w + 8 * m;
        int cB = w + 8 * (m + 1);
        const float4* rA = (const float4*)(fbh + (size_t)cA * HW);
        const float4* rB = (const float4*)(fbh + (size_t)cB * HW);
        float4 a0 = rA[lane], a1 = rA[lane + 32];
        float4 b0 = rB[lane], b1 = rB[lane + 32];
        float sA = wred(dot4(a0) + dot4(a1));
        float sB = wred(dot4(b0) + dot4(b1));
        if (lane == 0) {
            float r0 = 1.0f / fmaxf(sqrtf(sA), EPSV);
            float r1 = 1.0f / fmaxf(sqrtf(sB), EPSV);
            s_inv[cA] = r0; s_r2[cA] = pk2(r0 * r0, r0 * r0);
            s_inv[cB] = r1; s_r2[cB] = pk2(r1 * r1, r1 * r1);
        }
    }
    // ---- Pass 1b: prototype norms (warp w: k = w, w+8, w+16)
    for (int k = w; k < KK; k += 8) {
        float4 a = ((const float4*)(p + k * CC))[lane];
        float s = wred(dot4(a));
        if (lane == 0) {
            float inv = 1.0f / fmaxf(sqrtf(s), EPSV);
            s_pinv[k] = inv;
            s_pn2[k] = s * inv * inv;
        }
    }
    __syncthreads();

    // ---- Folded prototype table: s_pn[c*20 + k] = p[k][c] * pinv_k * inv_c (dup-packed)
    for (int i = tid; i < CC * KK; i += 256) {
        int c = i / KK, k = i - c * KK;
        float val = __ldg(p + k * CC + c) * s_pinv[k] * s_inv[c];
        s_pn[c * 20 + k] = pk2(val, val);
    }
    __syncthreads();

    // ---- Main dot loop: 32 c per thread, all 20 k, x loaded once per c.
    int pxg = tid & 63;
    int cq = tid >> 6;
    int c0 = cq * 32;

    const float4* fp = (const float4*)fbh + (size_t)c0 * (HW / 4) + pxg;
    const u64* pbase = s_pn + (size_t)c0 * 20;
    const u64* r2b = s_r2 + c0;

    u64 acc[2][20];
#pragma unroll
    for (int j = 0; j < 20; j++) { acc[0][j] = 0ull; acc[1][j] = 0ull; }
    u64 s2[2] = {0ull, 0ull};

#pragma unroll 4
    for (int t = 0; t < 32; t++) {
        float4 xv = fp[(size_t)t * (HW / 4)];
        u64 x0 = pk2(xv.x, xv.y);
        u64 x1 = pk2(xv.z, xv.w);
        const u64* pr = pbase + t * 20;
#pragma unroll
        for (int kk = 0; kk < 10; kk++) {
            ulonglong2 q = *(const ulonglong2*)(pr + 2 * kk);
            acc[0][2 * kk]     = fma2_(x0, q.x, acc[0][2 * kk]);
            acc[1][2 * kk]     = fma2_(x1, q.x, acc[1][2 * kk]);
            acc[0][2 * kk + 1] = fma2_(x0, q.y, acc[0][2 * kk + 1]);
            acc[1][2 * kk + 1] = fma2_(x1, q.y, acc[1][2 * kk + 1]);
        }
        u64 r2 = r2b[t];
        s2[0] = fma2_(mul2_(x0, r2), x0, s2[0]);
        s2[1] = fma2_(mul2_(x1, r2), x1, s2[1]);
    }

    // ---- s2 reduction across the 4 cq quarters
    s_s2p[(size_t)cq * 128 + 2 * pxg]     = s2[0];
    s_s2p[(size_t)cq * 128 + 2 * pxg + 1] = s2[1];
    __syncthreads();
    if (tid < 128) {
        u64 t = 0ull;
#pragma unroll
        for (int g = 0; g < 4; g++) t = add2_(t, s_s2p[g * 128 + tid]);
        s_s2[tid] = t;
    }

    // ---- Cross-cq dot reduction + epilogue, 5 k-chunks of 4 (aliases dead s_pn;
    //      fully unrolled so acc indices stay compile-time constants).
    u64* s_red = s_pn;           // [256 writers][4 k][2 pairs] u64 = 16 KB
    float scale = fabsf(ds[0]);
#pragma unroll
    for (int chunk = 0; chunk < 5; chunk++) {
        __syncthreads();
        u64* wr = s_red + (size_t)tid * 8;
#pragma unroll
        for (int kk = 0; kk < 4; kk++) {
            wr[2 * kk]     = acc[0][chunk * 4 + kk];
            wr[2 * kk + 1] = acc[1][chunk * 4 + kk];
        }
        __syncthreads();
        {
            int kk = tid >> 6;           // 0..3
            int pxg2 = tid & 63;
            u64 a0 = 0ull, a1 = 0ull;
#pragma unroll
            for (int g = 0; g < 4; g++) {
                ulonglong2 q = *(const ulonglong2*)(s_red + ((size_t)(g * 64 + pxg2) * 4 + kk) * 2);
                a0 = add2_(a0, q.x);
                a1 = add2_(a1, q.y);
            }
            int k = chunk * 4 + kk;
            float n0, n1, n2, n3;
            upk2(s_s2[2 * pxg2], n0, n1);
            upk2(s_s2[2 * pxg2 + 1], n2, n3);
            float qq = s_pn2[k];
            float d0, d1, d2, d3;
            upk2(a0, d0, d1);
            upk2(a1, d2, d3);
            float4 o;
            o.x = -scale * sqrtf(fmaxf(n0 + qq - 2.0f * d0, 0.0f));
            o.y = -scale * sqrtf(fmaxf(n1 + qq - 2.0f * d1, 0.0f));
            o.z = -scale * sqrtf(fmaxf(n2 + qq - 2.0f * d2, 0.0f));
            o.w = -scale * sqrtf(fmaxf(n3 + qq - 2.0f * d3, 0.0f));
            *(float4*)(out + ((size_t)b * KK + k) * HW + (size_t)h * WW + 4 * pxg2) = o;
        }
    }
}

extern "C" void kernel_launch(void* const* d_in, const int* in_sizes, int n_in,
                              void* d_out, int out_size) {
    const float* features   = (const float*)d_in[0];
    const float* prototypes = (const float*)d_in[1];
    const float* dscale     = (const float*)d_in[2];
    float* out = (float*)d_out;

    iso_kernel<<<BB * HH, 256>>>(features, prototypes, dscale, out);
}

// round 14
// speedup vs baseline: 1.4250x; 1.4250x over previous
#include <cuda_runtime.h>

#define BB 2
#define CC 128
#define HH 128
#define WW 256
#define KK 20
#define HW (HH * WW)
#define EPSV 1e-12f

typedef unsigned long long u64;

__device__ __forceinline__ u64 pk2(float lo, float hi) {
    u64 r; asm("mov.b64 %0, {%1,%2};" : "=l"(r) : "f"(lo), "f"(hi)); return r;
}
__device__ __forceinline__ void upk2(u64 v, float& lo, float& hi) {
    asm("mov.b64 {%0,%1}, %2;" : "=f"(lo), "=f"(hi) : "l"(v));
}
__device__ __forceinline__ u64 fma2_(u64 a, u64 b, u64 c) {
    u64 d; asm("fma.rn.f32x2 %0, %1, %2, %3;" : "=l"(d) : "l"(a), "l"(b), "l"(c)); return d;
}
__device__ __forceinline__ u64 mul2_(u64 a, u64 b) {
    u64 d; asm("mul.rn.f32x2 %0, %1, %2;" : "=l"(d) : "l"(a), "l"(b)); return d;
}
__device__ __forceinline__ u64 add2_(u64 a, u64 b) {
    u64 d; asm("add.rn.f32x2 %0, %1, %2;" : "=l"(d) : "l"(a), "l"(b)); return d;
}
#define HALF_BAR(id) asm volatile("bar.sync %0, %1;" :: "r"(id), "r"(256) : "memory")

__device__ __forceinline__ float wred(float v) {
#pragma unroll
    for (int o = 16; o > 0; o >>= 1) v += __shfl_xor_sync(0xffffffffu, v, o);
    return v;
}
__device__ __forceinline__ float dot4(float4 a) {
    return a.x * a.x + a.y * a.y + a.z * a.z + a.w * a.w;
}

// 16-c chunk with 4-deep LDG prefetch pipeline (r10, champion). Padded proto
// rows -> 2x LDS.128 + 1x LDS.64 per c. DO_S2 chunks also accumulate ||fn||^2.
template <bool DO_S2>
__device__ __forceinline__ void chunk16(const float4* __restrict__ fp, int ccb,
                                        const u64* __restrict__ pb,     // s_pn + (c0*4+kg)*6
                                        const u64* __restrict__ r2b,    // s_r2 + c0
                                        u64 acc[2][5], u64 s2[2]) {
    float4 xb[4];
#pragma unroll
    for (int j = 0; j < 4; j++) xb[j] = fp[(size_t)(ccb + j) * (HW / 4)];

#pragma unroll
    for (int t = 0; t < 16; t++) {
        int cc = ccb + t;
        float4 xv = xb[t & 3];
        if (t < 12) xb[t & 3] = fp[(size_t)(cc + 4) * (HW / 4)];

        u64 x0 = pk2(xv.x, xv.y);
        u64 x1 = pk2(xv.z, xv.w);
        const u64* pr = pb + cc * 24;
        ulonglong2 q0 = *(const ulonglong2*)(pr);
        ulonglong2 q1 = *(const ulonglong2*)(pr + 2);
        u64 p4 = pr[4];
        acc[0][0] = fma2_(x0, q0.x, acc[0][0]);
        acc[1][0] = fma2_(x1, q0.x, acc[1][0]);
        acc[0][1] = fma2_(x0, q0.y, acc[0][1]);
        acc[1][1] = fma2_(x1, q0.y, acc[1][1]);
        acc[0][2] = fma2_(x0, q1.x, acc[0][2]);
        acc[1][2] = fma2_(x1, q1.x, acc[1][2]);
        acc[0][3] = fma2_(x0, q1.y, acc[0][3]);
        acc[1][3] = fma2_(x1, q1.y, acc[1][3]);
        acc[0][4] = fma2_(x0, p4, acc[0][4]);
        acc[1][4] = fma2_(x1, p4, acc[1][4]);
        if (DO_S2) {
            u64 r2 = r2b[cc];
            s2[0] = fma2_(mul2_(x0, r2), x0, s2[0]);
            s2[1] = fma2_(mul2_(x1, r2), x1, s2[1]);
        }
    }
}

// Fused kernel (r10 structure + split-half prologue). Block = (b,h), 512 threads.
// tid: pxg bits0-5 (64 x 4 px), kg bits6-7 (4 x 5 k), ch bit8 (c-half).
// Prologue (norms + proto fold) is done per c-half with named barriers so each
// half starts its dot loop without waiting for the other half's DRAM reads.
__global__ __launch_bounds__(512, 2) void iso_kernel(const float* __restrict__ f,
                                                     const float* __restrict__ p,
                                                     const float* __restrict__ ds,
                                                     float* __restrict__ out) {
    __shared__ u64 s_pn[CC * 24];    // padded folded protos (24 KB); aliased for ch1 partials
    __shared__ u64 s_s2p[8 * 128];   // s2 partials per (ch*4+kg) group (8 KB)
    __shared__ u64 s_r2[CC];         // inv_c^2 dup-packed
    __shared__ float s_inv[CC];
    __shared__ float s_pinv[2][KK];  // per-half copy (identical values; avoids cross-half race)
    __shared__ float s_pn2[KK];
    __shared__ float s_scale;

    int tid = threadIdx.x;
    int lane = tid & 31;
    int b = blockIdx.x / HH, h = blockIdx.x % HH;
    const float* fbh = f + (size_t)b * CC * HW + (size_t)h * WW;

    int pxg = tid & 63;
    int kg = (tid >> 6) & 3;
    int ch = tid >> 8;
    int c0 = ch * 64;
    int wl = (tid >> 5) & 7;         // warp index within the half (0..7)

    if (tid == 0) s_scale = fabsf(ds[0]);

    // ---- Prologue (per half): W-norms for c in [c0, c0+64).
    // Warp wl handles c = c0 + wl + 8j + 32jb (8 c/warp, 4-row MLP batches).
#pragma unroll
    for (int jb = 0; jb < 2; jb++) {
        float4 v[8];
        int cbase = c0 + wl + jb * 32;
#pragma unroll
        for (int j = 0; j < 4; j++) {
            const float4* r4 = (const float4*)(fbh + (size_t)(cbase + 8 * j) * HW);
            v[2 * j]     = r4[lane];
            v[2 * j + 1] = r4[lane + 32];
        }
#pragma unroll
        for (int j = 0; j < 4; j++) {
            float s = wred(dot4(v[2 * j]) + dot4(v[2 * j + 1]));
            if (lane == 0) {
                int c = cbase + 8 * j;
                float r = 1.0f / fmaxf(sqrtf(s), EPSV);
                s_inv[c] = r;
                s_r2[c] = pk2(r * r, r * r);
            }
        }
    }
    // ---- Prototype norms, redundantly per half (identical deterministic values).
    for (int k = wl; k < KK; k += 8) {
        float4 a = ((const float4*)(p + k * CC))[lane];
        float s = wred(dot4(a));
        if (lane == 0) {
            float inv = 1.0f / fmaxf(sqrtf(s), EPSV);
            s_pinv[ch][k] = inv;
            if (ch == 0) s_pn2[k] = s * inv * inv;
        }
    }
    HALF_BAR(1 + ch);

    // ---- Fold protos for this half's 64 c: s_pn[(c*4+kg)*6+j]
    for (int i = tid & 255; i < 64 * KK; i += 256) {
        int cl = i / KK, k = i - cl * KK;
        int c = c0 + cl;
        int kg_ = k / 5, j = k - kg_ * 5;
        float val = __ldg(p + k * CC + c) * s_pinv[ch][k] * s_inv[c];
        s_pn[(c * 4 + kg_) * 6 + j] = pk2(val, val);
    }
    HALF_BAR(1 + ch);

    // ---- Main dot loop (r10: 4-deep prefetch)
    const float4* fp = (const float4*)fbh + (size_t)c0 * (HW / 4) + pxg;
    const u64* pb = s_pn + (size_t)(c0 * 4 + kg) * 6;
    const u64* r2b = s_r2 + c0;

    u64 acc[2][5];
#pragma unroll
    for (int j = 0; j < 5; j++) { acc[0][j] = 0ull; acc[1][j] = 0ull; }
    u64 s2[2] = {0ull, 0ull};

#pragma unroll
    for (int seg = 0; seg < 4; seg++) {
        if (seg == kg) chunk16<true>(fp, seg * 16, pb, r2b, acc, s2);
        else           chunk16<false>(fp, seg * 16, pb, r2b, acc, s2);
    }

    // ---- Reductions (full-block; alias dead s_pn for ch1 dot partials)
    s_s2p[(size_t)(ch * 4 + kg) * 128 + 2 * pxg]     = s2[0];
    s_s2p[(size_t)(ch * 4 + kg) * 128 + 2 * pxg + 1] = s2[1];
    __syncthreads();            // all threads done with s_pn reads
    u64* s_red = s_pn;          // [256 threads][10]
    if (ch == 1) {
        u64* r = s_red + (size_t)(tid & 255) * 10;
#pragma unroll
        for (int i = 0; i < 2; i++)
#pragma unroll
            for (int j = 0; j < 5; j++) r[i * 5 + j] = acc[i][j];
    }
    __syncthreads();

    if (ch == 0) {
        const u64* r = s_red + (size_t)tid * 10;
#pragma unroll
        for (int i = 0; i < 2; i++)
#pragma unroll
            for (int j = 0; j < 5; j++) acc[i][j] = add2_(acc[i][j], r[i * 5 + j]);

        u64 t0 = 0ull, t1 = 0ull;
#pragma unroll
        for (int g = 0; g < 8; g++) {
            t0 = add2_(t0, s_s2p[g * 128 + 2 * pxg]);
            t1 = add2_(t1, s_s2p[g * 128 + 2 * pxg + 1]);
        }
        float n0, n1, n2, n3;
        upk2(t0, n0, n1);
        upk2(t1, n2, n3);

        float scale = s_scale;
        float* ob = out + (size_t)b * KK * HW + (size_t)h * WW + 4 * pxg;
#pragma unroll
        for (int j = 0; j < 5; j++) {
            int k = kg * 5 + j;
            float q = s_pn2[k];
            float d0, d1, d2, d3;
            upk2(acc[0][j], d0, d1);
            upk2(acc[1][j], d2, d3);
            float4 o;
            o.x = -scale * sqrtf(fmaxf(n0 + q - 2.0f * d0, 0.0f));
            o.y = -scale * sqrtf(fmaxf(n1 + q - 2.0f * d1, 0.0f));
            o.z = -scale * sqrtf(fmaxf(n2 + q - 2.0f * d2, 0.0f));
            o.w = -scale * sqrtf(fmaxf(n3 + q - 2.0f * d3, 0.0f));
            *(float4*)(ob + (size_t)k * HW) = o;
        }
    }
}

extern "C" void kernel_launch(void* const* d_in, const int* in_sizes, int n_in,
                              void* d_out, int out_size) {
    const float* features   = (const float*)d_in[0];
    const float* prototypes = (const float*)d_in[1];
    const float* dscale     = (const float*)d_in[2];
    float* out = (float*)d_out;

    iso_kernel<<<BB * HH, 512>>>(features, prototypes, dscale, out);
}